// round 16
// baseline (speedup 1.0000x reference)
#include <cuda_runtime.h>
#include <cuda_fp16.h>
#include <math.h>
#include <stdint.h>

#define BATCH 16
#define CIN   192
#define CHID  384
#define HEADS 8
#define HDIM  48
#define IMG   56
#define HW    3136
#define KS    7

// ---------------- scratch ----------------
__device__ float g_qWkT[HEADS * CIN];
__device__ float g_biasq[HEADS];
__device__ float g_rpeexp[HEADS * 49];
__device__ __half g_wvh[CHID * CIN];
__device__ __half g_woh[CHID * CHID];
__device__ __half g_V[(size_t)BATCH * CHID * HW];
__device__ float  g_COSTE[(size_t)BATCH * HEADS * HW];
__device__ __half g_OUTPRE[(size_t)BATCH * CHID * HW];

__device__ __forceinline__ uint32_t smem_u32(const void* p) {
    uint32_t a;
    asm("{ .reg .u64 t; cvta.to.shared.u64 t, %1; cvt.u32.u64 %0, t; }" : "=r"(a) : "l"(p));
    return a;
}
__device__ __forceinline__ uint32_t packh2(float x, float y) {
    __half2 h = __floats2half2_rn(x, y);
    return *reinterpret_cast<uint32_t*>(&h);
}

// ---------------- K0: prep ----------------
__global__ void prep_kernel(const float* __restrict__ query,
                            const float* __restrict__ Wk,
                            const float* __restrict__ Wk_bias,
                            const float* __restrict__ rpe) {
    __shared__ float sq[CHID];
    __shared__ float snorm[HEADS];
    int tid = threadIdx.x;
    float inv = 1.0f / (sqrtf((float)HDIM) + 1e-6f);
    if (tid < CHID) sq[tid] = query[tid] * inv;
    __syncthreads();
    if (tid < HEADS) {
        float s = 0.f;
        for (int d = 0; d < HDIM; d++) { float v = sq[tid * HDIM + d]; s += v * v; }
        snorm[tid] = sqrtf(s) + 1e-6f;
    }
    __syncthreads();
    if (tid < CHID) sq[tid] = sq[tid] / snorm[tid / HDIM];
    __syncthreads();
    for (int e = tid; e < HEADS * CIN; e += blockDim.x) {
        int h = e / CIN, D = e % CIN;
        float s = 0.f;
        #pragma unroll 8
        for (int d = 0; d < HDIM; d++)
            s += sq[h * HDIM + d] * Wk[(size_t)D * CHID + h * HDIM + d];
        g_qWkT[e] = s;
    }
    if (tid < HEADS) {
        float s = 0.f;
        for (int d = 0; d < HDIM; d++)
            s += Wk_bias[tid * HDIM + d] * sq[tid * HDIM + d];
        g_biasq[tid] = s;
    }
    for (int e = tid; e < HEADS * 49; e += blockDim.x)
        g_rpeexp[e] = expf(rpe[e]);
}

// ---------------- weight conversion ----------------
__global__ __launch_bounds__(256)
void convw_kernel(const float* __restrict__ wv, const float* __restrict__ wo) {
    int gid = blockIdx.x * 256 + threadIdx.x;
    int nth = gridDim.x * 256;
    for (int i = gid; i < CHID * CIN; i += nth) g_wvh[i] = __float2half_rn(wv[i]);
    for (int i = gid; i < CHID * CHID; i += nth) g_woh[i] = __float2half_rn(wo[i]);
}

// ---------------- shared GEMM config ----------------
#define BM 128
#define BN 128

// ---------------- GEMM1: half A(weights), fp32 B(x) -> half C (V) ----------
#define BK1 16
#define APB1 48
#define BPB 272
#define ASTG1 (BM * APB1)
#define BSTG1 (BK1 * BPB)

__global__ __launch_bounds__(128, 2)
void sgemm_v(const __half* __restrict__ A, const float* __restrict__ bias,
             const float* __restrict__ X, __half* __restrict__ C) {
    const int K = CIN;
    const int b  = blockIdx.z;
    const int m0 = blockIdx.y * BM;
    const int n0 = blockIdx.x * BN;
    const float* Xb = X + (size_t)b * K * HW;
    __half* Cb = C + (size_t)b * CHID * HW;

    __shared__ __align__(16) char sA[2][ASTG1];
    __shared__ __align__(16) char sB[2][BSTG1];

    const int tid  = threadIdx.x;
    const int warp = tid >> 5;
    const int lane = tid & 31;
    const int quad = lane >> 2;
    const int qi   = lane & 3;
    const int m_base = (warp & 1) * 64;
    const int n_base = (warp >> 1) * 64;

    const uint32_t uA = smem_u32(&sA[0][0]);
    const uint32_t uB = smem_u32(&sB[0][0]);
    const uint32_t aAddrBase = uA + (uint32_t)(m_base + (lane & 15)) * APB1 + (uint32_t)((lane >> 4) * 8) * 2;
    const uint32_t bAddrBase = uB + (uint32_t)(lane & 15) * BPB + (uint32_t)(n_base + (lane >> 4) * 8) * 2;

    float acc[4][8][4];
    #pragma unroll
    for (int i = 0; i < 4; i++)
        #pragma unroll
        for (int j = 0; j < 8; j++)
            #pragma unroll
            for (int r = 0; r < 4; r++) acc[i][j][r] = 0.f;

    uint4 aR[2];
    float4 bR[4];
    auto load_regs = [&](int k0) {
        #pragma unroll
        for (int p = 0; p < 2; p++) {
            int c = p * 128 + tid;
            int m = c >> 1, j = c & 1;
            aR[p] = *reinterpret_cast<const uint4*>(&A[(size_t)(m0 + m) * K + k0 + j * 8]);
        }
        #pragma unroll
        for (int p = 0; p < 4; p++) {
            int c = p * 128 + tid;
            int kr = c >> 5, nc = (c & 31) * 4;
            int col = n0 + nc; if (col > HW - 4) col = HW - 4;
            bR[p] = *reinterpret_cast<const float4*>(&Xb[(size_t)(k0 + kr) * HW + col]);
        }
    };
    auto store_stage = [&](int buf) {
        #pragma unroll
        for (int p = 0; p < 2; p++) {
            int c = p * 128 + tid;
            int m = c >> 1, j = c & 1;
            *reinterpret_cast<uint4*>(&sA[buf][m * APB1 + j * 16]) = aR[p];
        }
        #pragma unroll
        for (int p = 0; p < 4; p++) {
            int c = p * 128 + tid;
            int kr = c >> 5, nc = (c & 31) * 4;
            uint2 v = make_uint2(packh2(bR[p].x, bR[p].y), packh2(bR[p].z, bR[p].w));
            *reinterpret_cast<uint2*>(&sB[buf][kr * BPB + nc * 2]) = v;
        }
    };

    load_regs(0);
    store_stage(0);
    __syncthreads();

    const int T = K / BK1;
    for (int t = 0; t < T; t++) {
        const int buf = t & 1;
        if (t + 1 < T) load_regs((t + 1) * BK1);

        uint32_t af[4][4], bf[4][4];
        const uint32_t aOff = aAddrBase + (buf ? ASTG1 : 0);
        const uint32_t bOff = bAddrBase + (buf ? BSTG1 : 0);
        #pragma unroll
        for (int mt = 0; mt < 4; mt++)
            asm volatile("ldmatrix.sync.aligned.m8n8.x4.shared.b16 {%0,%1,%2,%3}, [%4];"
                : "=r"(af[mt][0]), "=r"(af[mt][1]), "=r"(af[mt][2]), "=r"(af[mt][3])
                : "r"(aOff + (uint32_t)(mt * 16) * APB1));
        #pragma unroll
        for (int j = 0; j < 4; j++)
            asm volatile("ldmatrix.sync.aligned.m8n8.x4.trans.shared.b16 {%0,%1,%2,%3}, [%4];"
                : "=r"(bf[j][0]), "=r"(bf[j][1]), "=r"(bf[j][2]), "=r"(bf[j][3])
                : "r"(bOff + (uint32_t)(j * 16) * 2));
        #pragma unroll
        for (int mt = 0; mt < 4; mt++)
            #pragma unroll
            for (int nt = 0; nt < 8; nt++) {
                const int j = nt >> 1, h = (nt & 1) * 2;
                asm volatile(
                    "mma.sync.aligned.m16n8k16.row.col.f32.f16.f16.f32 "
                    "{%0,%1,%2,%3}, {%4,%5,%6,%7}, {%8,%9}, {%0,%1,%2,%3};"
                    : "+f"(acc[mt][nt][0]), "+f"(acc[mt][nt][1]),
                      "+f"(acc[mt][nt][2]), "+f"(acc[mt][nt][3])
                    : "r"(af[mt][0]), "r"(af[mt][1]), "r"(af[mt][2]), "r"(af[mt][3]),
                      "r"(bf[j][h]), "r"(bf[j][h + 1]));
            }

        if (t + 1 < T) store_stage(1 - buf);
        __syncthreads();
    }

    #pragma unroll
    for (int mt = 0; mt < 4; mt++) {
        const int r = m0 + m_base + mt * 16 + quad;
        const float bi0 = bias[r];
        const float bi1 = bias[r + 8];
        #pragma unroll
        for (int nt = 0; nt < 8; nt++) {
            const int c = n0 + n_base + nt * 8 + qi * 2;
            if (c < HW) {
                __half2 v0 = __floats2half2_rn(acc[mt][nt][0] + bi0, acc[mt][nt][1] + bi0);
                __half2 v1 = __floats2half2_rn(acc[mt][nt][2] + bi1, acc[mt][nt][3] + bi1);
                *reinterpret_cast<__half2*>(&Cb[(size_t)r * HW + c]) = v0;
                *reinterpret_cast<__half2*>(&Cb[(size_t)(r + 8) * HW + c]) = v1;
            }
        }
    }
}

// ---------------- GEMM2: half A(weights), half B(OUTPRE) -> fp32 C ----------
#define BK2 32
#define APB2 80
#define ASTG2 (BM * APB2)
#define BSTG2 (BK2 * BPB)

__global__ __launch_bounds__(128, 2)
void sgemm_out(const __half* __restrict__ A, const float* __restrict__ bias,
               const __half* __restrict__ X, float* __restrict__ C, int bz0) {
    const int K = CHID;
    const int b  = blockIdx.z + bz0;
    const int m0 = blockIdx.y * BM;
    const int n0 = blockIdx.x * BN;
    const __half* Xb = X + (size_t)b * K * HW;
    float* Cb = C + (size_t)b * CHID * HW;

    __shared__ __align__(16) char sA[2][ASTG2];
    __shared__ __align__(16) char sB[2][BSTG2];

    const int tid  = threadIdx.x;
    const int warp = tid >> 5;
    const int lane = tid & 31;
    const int quad = lane >> 2;
    const int qi   = lane & 3;
    const int m_base = (warp & 1) * 64;
    const int n_base = (warp >> 1) * 64;

    const uint32_t uA = smem_u32(&sA[0][0]);
    const uint32_t uB = smem_u32(&sB[0][0]);
    const uint32_t aAddrBase = uA + (uint32_t)(m_base + (lane & 15)) * APB2 + (uint32_t)((lane >> 4) * 8) * 2;
    const uint32_t bAddrBase = uB + (uint32_t)(lane & 15) * BPB + (uint32_t)(n_base + (lane >> 4) * 8) * 2;

    float acc[4][8][4];
    #pragma unroll
    for (int i = 0; i < 4; i++)
        #pragma unroll
        for (int j = 0; j < 8; j++)
            #pragma unroll
            for (int r = 0; r < 4; r++) acc[i][j][r] = 0.f;

    uint4 aR[4], bR[4];
    auto load_regs = [&](int k0) {
        #pragma unroll
        for (int p = 0; p < 4; p++) {
            int c = p * 128 + tid;
            int m = c >> 2, j = c & 3;
            aR[p] = *reinterpret_cast<const uint4*>(&A[(size_t)(m0 + m) * K + k0 + j * 8]);
        }
        #pragma unroll
        for (int p = 0; p < 4; p++) {
            int c = p * 128 + tid;
            int kr = c >> 4, nc = (c & 15) * 8;
            int col = n0 + nc; if (col > HW - 8) col = HW - 8;
            bR[p] = *reinterpret_cast<const uint4*>(&Xb[(size_t)(k0 + kr) * HW + col]);
        }
    };
    auto store_stage = [&](int buf) {
        #pragma unroll
        for (int p = 0; p < 4; p++) {
            int c = p * 128 + tid;
            int m = c >> 2, j = c & 3;
            *reinterpret_cast<uint4*>(&sA[buf][m * APB2 + j * 16]) = aR[p];
        }
        #pragma unroll
        for (int p = 0; p < 4; p++) {
            int c = p * 128 + tid;
            int kr = c >> 4, nc = (c & 15) * 8;
            *reinterpret_cast<uint4*>(&sB[buf][kr * BPB + nc * 2]) = bR[p];
        }
    };

    load_regs(0);
    store_stage(0);
    __syncthreads();

    const int T = K / BK2;
    for (int t = 0; t < T; t++) {
        const int buf = t & 1;
        if (t + 1 < T) load_regs((t + 1) * BK2);

        const uint32_t aOff = aAddrBase + (buf ? ASTG2 : 0);
        const uint32_t bOff = bAddrBase + (buf ? BSTG2 : 0);
        #pragma unroll
        for (int h = 0; h < 2; h++) {
            uint32_t af[4][4], bf[4][4];
            #pragma unroll
            for (int mt = 0; mt < 4; mt++)
                asm volatile("ldmatrix.sync.aligned.m8n8.x4.shared.b16 {%0,%1,%2,%3}, [%4];"
                    : "=r"(af[mt][0]), "=r"(af[mt][1]), "=r"(af[mt][2]), "=r"(af[mt][3])
                    : "r"(aOff + (uint32_t)(mt * 16) * APB2 + (uint32_t)(h * 32)));
            #pragma unroll
            for (int j = 0; j < 4; j++)
                asm volatile("ldmatrix.sync.aligned.m8n8.x4.trans.shared.b16 {%0,%1,%2,%3}, [%4];"
                    : "=r"(bf[j][0]), "=r"(bf[j][1]), "=r"(bf[j][2]), "=r"(bf[j][3])
                    : "r"(bOff + (uint32_t)(j * 16) * 2 + (uint32_t)(h * 16) * BPB));
            #pragma unroll
            for (int mt = 0; mt < 4; mt++)
                #pragma unroll
                for (int nt = 0; nt < 8; nt++) {
                    const int j = nt >> 1, hh = (nt & 1) * 2;
                    asm volatile(
                        "mma.sync.aligned.m16n8k16.row.col.f32.f16.f16.f32 "
                        "{%0,%1,%2,%3}, {%4,%5,%6,%7}, {%8,%9}, {%0,%1,%2,%3};"
                        : "+f"(acc[mt][nt][0]), "+f"(acc[mt][nt][1]),
                          "+f"(acc[mt][nt][2]), "+f"(acc[mt][nt][3])
                        : "r"(af[mt][0]), "r"(af[mt][1]), "r"(af[mt][2]), "r"(af[mt][3]),
                          "r"(bf[j][hh]), "r"(bf[j][hh + 1]));
                }
        }

        if (t + 1 < T) store_stage(1 - buf);
        __syncthreads();
    }

    #pragma unroll
    for (int mt = 0; mt < 4; mt++) {
        const int r = m0 + m_base + mt * 16 + quad;
        const float bi0 = bias[r];
        const float bi1 = bias[r + 8];
        #pragma unroll
        for (int nt = 0; nt < 8; nt++) {
            const int c = n0 + n_base + nt * 8 + qi * 2;
            if (c < HW) {
                float2 v0 = make_float2(acc[mt][nt][0] + bi0, acc[mt][nt][1] + bi0);
                float2 v1 = make_float2(acc[mt][nt][2] + bi1, acc[mt][nt][3] + bi1);
                *reinterpret_cast<float2*>(&Cb[(size_t)r * HW + c]) = v0;
                *reinterpret_cast<float2*>(&Cb[(size_t)(r + 8) * HW + c]) = v1;
            }
        }
    }
}

// ---------------- cost kernel v2 ----------------
__global__ __launch_bounds__(512)
void cost_kernel(const float* __restrict__ x) {
    __shared__ float4 sW4[HEADS * CIN / 4];
    __shared__ float sb[HEADS];
    __shared__ float part[4][HEADS][128];

    const int tid = threadIdx.x;
    const int g   = tid >> 7;
    const int px  = tid & 127;

    const float4* gW4 = reinterpret_cast<const float4*>(g_qWkT);
    for (int i = tid; i < HEADS * CIN / 4; i += 512) sW4[i] = gW4[i];
    if (tid < HEADS) sb[tid] = g_biasq[tid];
    __syncthreads();

    const int gpix = blockIdx.x * 128 + px;
    const int b = gpix / HW, hw = gpix % HW;
    const float* xb = x + (size_t)b * CIN * HW + hw;

    float acc[HEADS] = {};
    const int d0 = g * (CIN / 4 / 4);
    #pragma unroll 4
    for (int D4 = d0; D4 < d0 + 12; D4++) {
        float x0 = xb[(size_t)(D4 * 4 + 0) * HW];
        float x1 = xb[(size_t)(D4 * 4 + 1) * HW];
        float x2 = xb[(size_t)(D4 * 4 + 2) * HW];
        float x3 = xb[(size_t)(D4 * 4 + 3) * HW];
        #pragma unroll
        for (int h = 0; h < HEADS; h++) {
            float4 w = sW4[h * (CIN / 4) + D4];
            acc[h] += x0 * w.x + x1 * w.y + x2 * w.z + x3 * w.w;
        }
    }
    #pragma unroll
    for (int h = 0; h < HEADS; h++) part[g][h][px] = acc[h];
    __syncthreads();

    if (tid < 128) {
        float* cb = g_COSTE + (size_t)b * HEADS * HW + hw;
        #pragma unroll
        for (int h = 0; h < HEADS; h++) {
            float s = part[0][h][px] + part[1][h][px] + part[2][h][px] + part[3][h][px];
            cb[(size_t)h * HW] = expf(s + sb[h]);
        }
    }
}

// ---------------- dwconv kernel ----------------
#define DP 68

__global__ __launch_bounds__(256)
void dwconv_kernel(int bofs) {
    const int bidx = blockIdx.x + bofs;
    const int cg = bidx & 3;
    const int head = (bidx >> 2) & 7;
    const int b = bidx >> 5;

    __shared__ __align__(16) float sc[62 * DP];
    __shared__ __align__(16) float scv[62 * DP];

    const int tid = threadIdx.x;

    float wr[49];
    #pragma unroll
    for (int i = 0; i < 49; i++) wr[i] = g_rpeexp[head * 49 + i];

    const float* cp = g_COSTE + ((size_t)b * HEADS + head) * HW;
    for (int i = tid; i < 62 * DP; i += 256) {
        int r = i / DP, c = i % DP;
        int y = r - 3, x = c - 4;
        float v = 0.f;
        if ((unsigned)y < 56u && (unsigned)x < 56u) v = cp[y * 56 + x];
        sc[i] = v;
        scv[i] = 0.f;
    }
    __syncthreads();

    const int y0 = (tid / 14) * 4;
    const int x0 = (tid % 14) * 4;
    const bool active = tid < 196;

    float4 rden[4];
    if (active) {
        float acc[4][4] = {};
        #pragma unroll
        for (int i = 0; i < 10; i++) {
            const float* base = &sc[(y0 + i) * DP + x0];
            float4 q0 = *reinterpret_cast<const float4*>(base);
            float4 q1 = *reinterpret_cast<const float4*>(base + 4);
            float4 q2 = *reinterpret_cast<const float4*>(base + 8);
            float r[12] = {q0.x, q0.y, q0.z, q0.w, q1.x, q1.y, q1.z, q1.w,
                           q2.x, q2.y, q2.z, q2.w};
            #pragma unroll
            for (int oy = 0; oy < 4; oy++) {
                const int wi = i - oy;
                if (wi >= 0 && wi < 7) {
                    #pragma unroll
                    for (int j = 0; j < 7; j++) {
                        float wv = wr[wi * 7 + j];
                        acc[oy][0] += wv * r[j + 1];
                        acc[oy][1] += wv * r[j + 2];
                        acc[oy][2] += wv * r[j + 3];
                        acc[oy][3] += wv * r[j + 4];
                    }
                }
            }
        }
        #pragma unroll
        for (int oy = 0; oy < 4; oy++)
            rden[oy] = make_float4(1.f / acc[oy][0], 1.f / acc[oy][1],
                                   1.f / acc[oy][2], 1.f / acc[oy][3]);
    }

    for (int c = 0; c < 12; c++) {
        const int ch = head * HDIM + cg * 12 + c;
        const __half* vp = g_V + ((size_t)b * CHID + ch) * HW;
        __syncthreads();
        for (int i = tid; i < 784; i += 256) {
            int y = i / 14, c4 = (i % 14) * 4;
            uint2 raw = *reinterpret_cast<const uint2*>(&vp[y * 56 + c4]);
            float2 f0 = __half22float2(*reinterpret_cast<__half2*>(&raw.x));
            float2 f1 = __half22float2(*reinterpret_cast<__half2*>(&raw.y));
            float4 s = *reinterpret_cast<const float4*>(&sc[(y + 3) * DP + 4 + c4]);
            float4 o = make_float4(f0.x * s.x, f0.y * s.y, f1.x * s.z, f1.y * s.w);
            *reinterpret_cast<float4*>(&scv[(y + 3) * DP + 4 + c4]) = o;
        }
        __syncthreads();
        if (active) {
            float acc[4][4] = {};
            #pragma unroll
            for (int i = 0; i < 10; i++) {
                const float* base = &scv[(y0 + i) * DP + x0];
                float4 q0 = *reinterpret_cast<const float4*>(base);
                float4 q1 = *reinterpret_cast<const float4*>(base + 4);
                float4 q2 = *reinterpret_cast<const float4*>(base + 8);
                float r[12] = {q0.x, q0.y, q0.z, q0.w, q1.x, q1.y, q1.z, q1.w,
                               q2.x, q2.y, q2.z, q2.w};
                #pragma unroll
                for (int oy = 0; oy < 4; oy++) {
                    const int wi = i - oy;
                    if (wi >= 0 && wi < 7) {
                        #pragma unroll
                        for (int j = 0; j < 7; j++) {
                            float wv = wr[wi * 7 + j];
                            acc[oy][0] += wv * r[j + 1];
                            acc[oy][1] += wv * r[j + 2];
                            acc[oy][2] += wv * r[j + 3];
                            acc[oy][3] += wv * r[j + 4];
                        }
                    }
                }
            }
            __half* op = g_OUTPRE + ((size_t)b * CHID + ch) * HW;
            #pragma unroll
            for (int oy = 0; oy < 4; oy++) {
                __half2 o0 = __floats2half2_rn(acc[oy][0] * rden[oy].x, acc[oy][1] * rden[oy].y);
                __half2 o1 = __floats2half2_rn(acc[oy][2] * rden[oy].z, acc[oy][3] * rden[oy].w);
                uint2 pk = make_uint2(*reinterpret_cast<uint32_t*>(&o0),
                                      *reinterpret_cast<uint32_t*>(&o1));
                *reinterpret_cast<uint2*>(&op[(y0 + oy) * 56 + x0]) = pk;
            }
        }
    }
}

// ---------------- launch ----------------
extern "C" void kernel_launch(void* const* d_in, const int* in_sizes, int n_in,
                              void* d_out, int out_size) {
    const float* x        = (const float*)d_in[0];
    const float* query    = (const float*)d_in[1];
    const float* Wk       = (const float*)d_in[2];
    const float* Wk_bias  = (const float*)d_in[3];
    const float* to_v_w   = (const float*)d_in[4];
    const float* to_v_b   = (const float*)d_in[5];
    const float* to_out_w = (const float*)d_in[6];
    const float* to_out_b = (const float*)d_in[7];
    const float* rpe      = (const float*)d_in[8];

    static __half* pV = nullptr;
    static __half* pOUTPRE = nullptr;
    static __half* pWVH = nullptr;
    static __half* pWOH = nullptr;
    static cudaStream_t s2 = nullptr;
    static cudaEvent_t eFork = nullptr, eC = nullptr, eG1 = nullptr,
                       eDw0 = nullptr, eJ = nullptr;
    if (!pV) {
        cudaGetSymbolAddress((void**)&pV, g_V);
        cudaGetSymbolAddress((void**)&pOUTPRE, g_OUTPRE);
        cudaGetSymbolAddress((void**)&pWVH, g_wvh);
        cudaGetSymbolAddress((void**)&pWOH, g_woh);
        cudaStreamCreateWithFlags(&s2, cudaStreamNonBlocking);
        cudaEventCreateWithFlags(&eFork, cudaEventDisableTiming);
        cudaEventCreateWithFlags(&eC, cudaEventDisableTiming);
        cudaEventCreateWithFlags(&eG1, cudaEventDisableTiming);
        cudaEventCreateWithFlags(&eDw0, cudaEventDisableTiming);
        cudaEventCreateWithFlags(&eJ, cudaEventDisableTiming);
    }

    prep_kernel<<<1, 384>>>(query, Wk, Wk_bias, rpe);
    convw_kernel<<<128, 256>>>(to_v_w, to_out_w);

    cudaEventRecord(eFork, 0);
    cudaStreamWaitEvent(s2, eFork, 0);

    dim3 ggrid((HW + BN - 1) / BN, CHID / BM, BATCH);      // gemm1: all batches
    sgemm_v<<<ggrid, 128>>>(pWVH, to_v_b, x, pV);
    cudaEventRecord(eG1, 0);

    cost_kernel<<<(BATCH * HW) / 128, 512, 0, s2>>>(x);
    cudaEventRecord(eC, s2);

    // stream 0: dwconv half0 (b 0..7) then gemm2 half0
    cudaStreamWaitEvent(0, eC, 0);
    dwconv_kernel<<<256, 256>>>(0);
    cudaEventRecord(eDw0, 0);

    // stream s2: after gemm1 + dw0, dwconv half1 overlaps gemm2 half0
    cudaStreamWaitEvent(s2, eG1, 0);
    cudaStreamWaitEvent(s2, eDw0, 0);
    dwconv_kernel<<<256, 256, 0, s2>>>(256);

    dim3 g2half((HW + BN - 1) / BN, CHID / BM, BATCH / 2); // (25, 3, 8)
    sgemm_out<<<g2half, 128>>>(pWOH, to_out_b, pOUTPRE, (float*)d_out, 0);
    sgemm_out<<<g2half, 128, 0, s2>>>(pWOH, to_out_b, pOUTPRE, (float*)d_out, 8);

    cudaEventRecord(eJ, s2);
    cudaStreamWaitEvent(0, eJ, 0);
}